// round 5
// baseline (speedup 1.0000x reference)
#include <cuda_runtime.h>
#include <math.h>

// PennyLaneBasicDQN: 16-qubit VQC (RY embed + 4x[Rot,CZ chain]) + linear head.
// Heisenberg light-cone + Pauli-transfer-matrix method (verified R3/R4).
// R5: 256-thread CTAs, grid (16 qubits x 8 sample-chunks); 4 threads per
// sample in the contraction (axis-0 slices, bank-conflict-free padded layout);
// column-parallel PTM prologue; fused last-CTA FC head.

#define NQ 16
#define NA 6
#define BATCHSZ 512
#define NCHUNK 8
#define SPC 64            // samples per chunk
#define APAD 264          // padded a-slice stride (floats): 264%32=8 -> no conflicts

__device__ float g_z[BATCHSZ * NQ];
__device__ int   g_cnt[NCHUNK] = {0};

struct C2 { float x, y; };
__device__ __forceinline__ C2 cmk(float a, float b){ C2 r; r.x=a; r.y=b; return r; }
__device__ __forceinline__ C2 cml(C2 a, C2 b){ return cmk(a.x*b.x - a.y*b.y, a.x*b.y + a.y*b.x); }
__device__ __forceinline__ C2 cad(C2 a, C2 b){ return cmk(a.x+b.x, a.y+b.y); }

// Column p of the 4x4 real PTM of conjugation O -> U^dag O U:
//   col[q] = M[q][p] = 0.5 * Re Tr[ sigma_q U^dag sigma_p U ]
__device__ __forceinline__ void ptm_col(const C2 u[4], int p, float col[4]) {
    C2 ud00 = cmk(u[0].x, -u[0].y), ud01 = cmk(u[2].x, -u[2].y);
    C2 ud10 = cmk(u[1].x, -u[1].y), ud11 = cmk(u[3].x, -u[3].y);
    C2 s00, s01, s10, s11;                 // sigma_p * U
    if (p == 0)      { s00=u[0]; s01=u[1]; s10=u[2]; s11=u[3]; }
    else if (p == 1) { s00=u[2]; s01=u[3]; s10=u[0]; s11=u[1]; }
    else if (p == 2) {                      // Y = [[0,-i],[i,0]]
        s00 = cmk( u[2].y, -u[2].x);
        s01 = cmk( u[3].y, -u[3].x);
        s10 = cmk(-u[0].y,  u[0].x);
        s11 = cmk(-u[1].y,  u[1].x);
    } else           { s00=u[0]; s01=u[1]; s10=cmk(-u[2].x,-u[2].y); s11=cmk(-u[3].x,-u[3].y); }
    C2 A00 = cad(cml(ud00, s00), cml(ud01, s10));
    C2 A01 = cad(cml(ud00, s01), cml(ud01, s11));
    C2 A10 = cad(cml(ud10, s00), cml(ud11, s10));
    C2 A11 = cad(cml(ud10, s01), cml(ud11, s11));
    col[0] = 0.5f*(A00.x + A11.x);
    col[1] = 0.5f*(A01.x + A10.x);
    col[2] = 0.5f*(A10.y - A01.y);
    col[3] = 0.5f*(A00.x - A11.x);
}

// PennyLane Rot(phi,theta,omega) = RZ(omega) RY(theta) RZ(phi)
__device__ __forceinline__ void rot_u(const float* wp, C2 u[4]) {
    float phi = wp[0], th = wp[1], om = wp[2];
    float c, s; __sincosf(0.5f*th, &s, &c);
    float epx, epy, emx, emy;
    __sincosf(-0.5f*(phi+om), &epy, &epx);   // ep = exp(-i(phi+om)/2)
    __sincosf(-0.5f*(phi-om), &emy, &emx);   // em = exp(-i(phi-om)/2)
    u[0] = cmk( epx*c,  epy*c);
    u[1] = cmk(-emx*s,  emy*s);
    u[2] = cmk( emx*s,  emy*s);
    u[3] = cmk( epx*c, -epy*c);
}

__global__ __launch_bounds__(256)
void vqc_fused(const float* __restrict__ x, const float* __restrict__ W,
               const float* __restrict__ fcw, const float* __restrict__ fcb,
               float* __restrict__ out)
{
    __shared__ __align__(16) float tA[4 * APAD];
    __shared__ __align__(16) float tB[4 * APAD];
    __shared__ float PT[15][16];          // conj-PTMs: layers 1..3 x window pos 0..4
    __shared__ float bx[7][3], bz[7][3];  // layer-0 Bloch columns, wires i-3..i+3
    __shared__ int s_elect;

    const int i     = blockIdx.x;         // measured qubit
    const int chunk = blockIdx.y;         // 64-sample chunk
    const int tid   = threadIdx.x;
    const int sl    = tid >> 2;           // local sample 0..63
    const int as    = tid & 3;            // axis-0 slice
    const int b     = chunk * SPC + sl;

    // issue x loads early (DRAM latency hidden behind prologue + barrier)
    float xv[7];
    #pragma unroll
    for (int k = 0; k < 7; k++) {
        int w = i - 3 + k;
        xv[k] = (w >= 0 && w < NQ) ? x[b*NQ + w] : 0.f;
    }

    // ---- prologue: column-parallel PTM + Bloch construction ----
    if (tid < 60) {
        int id = tid >> 2, p = tid & 3;        // PTM id 0..14, column p
        int l = 1 + id / 5, a = id % 5;
        int w = i - 2 + a;
        float col[4];
        if (w >= 0 && w < NQ) {
            C2 u[4]; rot_u(W + (l*NQ + w)*3, u);
            ptm_col(u, p, col);
        } else {
            #pragma unroll
            for (int q = 0; q < 4; q++) col[q] = (q == p) ? 1.f : 0.f;
        }
        #pragma unroll
        for (int q = 0; q < 4; q++) PT[id][q*4 + p] = col[q];
    } else if (tid >= 64 && tid < 78) {
        int id = tid - 64;
        int k = id >> 1;                       // window wire slot 0..6
        int p = (id & 1) ? 3 : 1;              // column: 1 -> bx, 3 -> bz
        int w = i - 3 + k;
        float col[4] = {0.f, 0.f, 0.f, 0.f};
        if (w >= 0 && w < NQ) {
            C2 u[4]; rot_u(W + w*3, u);        // layer-0 Rot
            C2 v[4] = { cmk(u[0].x,-u[0].y), cmk(u[2].x,-u[2].y),
                        cmk(u[1].x,-u[1].y), cmk(u[3].x,-u[3].y) };  // U^dag
            ptm_col(v, p, col);
        }
        float* dstv = (p == 1) ? bx[k] : bz[k];
        dstv[0] = col[1]; dstv[1] = col[2]; dstv[2] = col[3];
    }
    for (int j = tid; j < 1024; j += 256) tA[j] = (j == 48) ? 1.f : 0.f; // Z at pos 2
    __syncthreads();

    // per-sample Bloch vectors
    float m[7][3];
    #pragma unroll
    for (int k = 0; k < 7; k++) {
        float sx, cx; __sincosf(xv[k], &sx, &cx);   // RY(x)|0> Bloch = (sx,0,cx)
        m[k][0] = sx*bx[k][0] + cx*bz[k][0];
        m[k][1] = sx*bx[k][1] + cx*bz[k][1];
        m[k][2] = sx*bx[k][2] + cx*bz[k][2];
    }

    // ---- backward conjugation: M(R3), CZ(D2), M(R2), CZ(D1), M(R1), CZ(D0) ----
    float* src = tA; float* dst = tB;
    for (int l = 3; l >= 1; l--) {
        #pragma unroll
        for (int a = 0; a < 5; a++) {
            const float* M = PT[(l-1)*5 + a];
            const int s = 1 << (2*(4-a));      // axis stride: 256,64,16,4,1
            int base = (tid / s) * (4*s) + (tid % s);   // exactly 1 fiber/thread
            float c0 = src[base], c1 = src[base+s], c2 = src[base+2*s], c3 = src[base+3*s];
            dst[base]     = M[0] *c0 + M[1] *c1 + M[2] *c2 + M[3] *c3;
            dst[base+s]   = M[4] *c0 + M[5] *c1 + M[6] *c2 + M[7] *c3;
            dst[base+2*s] = M[8] *c0 + M[9] *c1 + M[10]*c2 + M[11]*c3;
            dst[base+3*s] = M[12]*c0 + M[13]*c1 + M[14]*c2 + M[15]*c3;
            __syncthreads();
            float* t = src; src = dst; dst = t;
        }
        // CZ chain: np = xr? p^3:p ; nq = xl? q^3:q ; sign -1 iff xl&&xr&&p!=q.
        // Final CZ stage (l==1) scatters into the a-padded layout.
        const bool pad = (l == 1);
        #pragma unroll
        for (int r = 0; r < 4; r++) {
            int e = (tid << 2) | r;
            int p[5] = {(e>>8)&3, (e>>6)&3, (e>>4)&3, (e>>2)&3, e&3};
            float sg = src[e];
            #pragma unroll
            for (int a = 0; a < 4; a++) {
                int wl = i - 2 + a;
                if (wl >= 0 && wl + 1 < NQ) {
                    int pa = p[a], pb = p[a+1];
                    bool xl = (pa==1)||(pa==2), xr = (pb==1)||(pb==2);
                    if (xl && xr && pa != pb) sg = -sg;
                    if (xr) p[a]   = pa ^ 3;
                    if (xl) p[a+1] = pb ^ 3;
                }
            }
            int di = (p[0]<<8)|(p[1]<<6)|(p[2]<<4)|(p[3]<<2)|p[4];
            int o  = pad ? ((di >> 8) * APAD + (di & 255)) : di;
            dst[o] = sg;
        }
        __syncthreads();
        float* t = src; src = dst; dst = t;
    }
    // 18 stages (even count) -> final (padded) tensor in tA == src

    // ---- per-sample contraction: thread owns axis-0 slice `as` ----
    float dL = (i - 3 >= 0) ? m[0][2] : 1.f;   // D0 straddling-CZ dressings
    float dR = (i + 3 < NQ) ? m[6][2] : 1.f;
    float v0[4], v1[4], v2[4], v3[4], v4[4];
    v0[0]=1.f; v0[1]=dL*m[1][0]; v0[2]=dL*m[1][1]; v0[3]=m[1][2];
    v1[0]=1.f; v1[1]=m[2][0];    v1[2]=m[2][1];    v1[3]=m[2][2];
    v2[0]=1.f; v2[1]=m[3][0];    v2[2]=m[3][1];    v2[3]=m[3][2];
    v3[0]=1.f; v3[1]=m[4][0];    v3[2]=m[4][1];    v3[3]=m[4][2];
    v4[0]=1.f; v4[1]=dR*m[5][0]; v4[2]=dR*m[5][1]; v4[3]=m[5][2];

    const float4* Ta = reinterpret_cast<const float4*>(src + as * APAD);
    float sb[4];
    #pragma unroll
    for (int q = 0; q < 4; q++) {
        float acc = 0.f;
        #pragma unroll
        for (int c = 0; c < 4; c++) {
            float sc = 0.f;
            #pragma unroll
            for (int d = 0; d < 4; d++) {
                float4 t4 = Ta[q*16 + c*4 + d];
                sc += v3[d] * (t4.x*v4[0] + t4.y*v4[1] + t4.z*v4[2] + t4.w*v4[3]);
            }
            acc += v2[c] * sc;
        }
        sb[q] = acc;
    }
    float z = v0[as] * (v1[0]*sb[0] + v1[1]*sb[1] + v1[2]*sb[2] + v1[3]*sb[3]);
    z += __shfl_xor_sync(0xffffffffu, z, 1);
    z += __shfl_xor_sync(0xffffffffu, z, 2);
    if (as == 0) g_z[b * NQ + i] = z;

    // ---- fused FC head: last CTA of this chunk does the 64x6 GEMV ----
    __syncthreads();
    if (tid == 0) {
        __threadfence();
        int old = atomicAdd(&g_cnt[chunk], 1);
        int e = (old == NQ - 1);
        if (e) {
            __threadfence();
            atomicExch(&g_cnt[chunk], 0);   // reset for next graph replay
        }
        s_elect = e;
    }
    __syncthreads();
    if (s_elect) {
        // stage chunk's z-block into smem, then tiny GEMV
        for (int j = tid; j < SPC * NQ; j += 256)
            tA[j] = __ldcg(&g_z[chunk * SPC * NQ + j]);
        __syncthreads();
        for (int item = tid; item < SPC * NA; item += 256) {
            int s = item / NA, a = item % NA;
            float acc = fcb[a];
            #pragma unroll
            for (int k = 0; k < NQ; k++) acc += tA[s*NQ + k] * fcw[a*NQ + k];
            out[(chunk * SPC + s) * NA + a] = acc;
        }
    }
}

extern "C" void kernel_launch(void* const* d_in, const int* in_sizes, int n_in,
                              void* d_out, int out_size) {
    const float* x   = (const float*)d_in[0];   // [512,16]
    const float* W   = (const float*)d_in[1];   // [4,16,3]
    const float* fcw = (const float*)d_in[2];   // [6,16]
    const float* fcb = (const float*)d_in[3];   // [6]
    float* out = (float*)d_out;                 // [512,6]
    (void)in_sizes; (void)n_in; (void)out_size;
    dim3 grid(NQ, NCHUNK);
    vqc_fused<<<grid, 256>>>(x, W, fcw, fcb, out);
}